// round 4
// baseline (speedup 1.0000x reference)
#include <cuda_runtime.h>
#include <math.h>

#define MAX_NE 100000
#define MAX_NR 1000
#define MAX_E  1000000
#define PACK_CAP 1310784   // E + 3*N_E padding + 64 over-read guard

// ---------------- scratch ----------------
__device__ float  g_sh[MAX_NE];
__device__ float  g_st[MAX_NE];
__device__ float  g_sr[MAX_NR];
__device__ float  g_P[16 * MAX_NR * 32];   // [chunk(16)][rel][32]; h: 0..7, t: 8..15
__device__ int    g_cnt_h[MAX_NE];
__device__ int    g_cnt_t[MAX_NE];
__device__ int    g_starts_h[MAX_NE + 1];  // PADDED exclusive starts (multiples of 4 edges)
__device__ int    g_starts_t[MAX_NE + 1];
__device__ int    g_cur_h[MAX_NE];
__device__ int    g_cur_t[MAX_NE];
__device__ float  g_inv_h[MAX_NE];
__device__ float  g_inv_t[MAX_NE];
// pad slots are NEVER written: BSS-zero => {z=0, off=0}, mathematically inert.
__device__ float2 g_pack_h[PACK_CAP];
__device__ float2 g_pack_t[PACK_CAP];
__device__ int    g_bsum[2][160];

// ---------------- init ----------------
__global__ void k_zero(int n_e) {
    int i = blockIdx.x * blockDim.x + threadIdx.x;
    if (i < n_e) { g_cnt_h[i] = 0; g_cnt_t[i] = 0; }
}

// ---------------- fused attention scores (nodes then rels), warp per row ----------------
__global__ void k_scores(const float4* __restrict__ xe, const float4* __restrict__ xr,
                         const float4* __restrict__ wah4, const float4* __restrict__ wat4,
                         const float4* __restrict__ war4, int n_e, int n_r) {
    int gw = (blockIdx.x * blockDim.x + threadIdx.x) >> 5;
    int lane = threadIdx.x & 31;
    if (gw < n_e) {
        float4 v = xe[(size_t)gw * 32 + lane];
        float4 a = wah4[lane];
        float4 b = wat4[lane];
        float da = v.x * a.x + v.y * a.y + v.z * a.z + v.w * a.w;
        float db = v.x * b.x + v.y * b.y + v.z * b.z + v.w * b.w;
#pragma unroll
        for (int o = 16; o > 0; o >>= 1) {
            da += __shfl_xor_sync(0xffffffffu, da, o);
            db += __shfl_xor_sync(0xffffffffu, db, o);
        }
        if (lane == 0) { g_sh[gw] = da; g_st[gw] = db; }
    } else if (gw < n_e + n_r) {
        int r = gw - n_e;
        float4 v = xr[r * 32 + lane];
        float4 a = war4[lane];
        float d = v.x * a.x + v.y * a.y + v.z * a.z + v.w * a.w;
#pragma unroll
        for (int o = 16; o > 0; o >>= 1) d += __shfl_xor_sync(0xffffffffu, d, o);
        if (lane == 0) g_sr[r] = d;
    }
}

// ---------------- fused relation pipeline: x_r -> hid -> msg -> P tables ----------------
#define RPB 8
__global__ __launch_bounds__(256) void k_rgemm(const float* __restrict__ xr,
                                               const float* __restrict__ W1, const float* __restrict__ b1,
                                               const float* __restrict__ W2, const float* __restrict__ b2,
                                               const float* __restrict__ Wr, int n_r) {
    __shared__ float sx[RPB * 128];
    __shared__ float shid[RPB * 256];
    __shared__ float smsg[RPB * 128];
    __shared__ float wt[32 * 256];
    int r0 = blockIdx.x * RPB;
    int tid = threadIdx.x;

    for (int i = tid; i < RPB * 128; i += 256) {
        int rr = i >> 7, k = i & 127, r = r0 + rr;
        sx[i] = (r < n_r) ? xr[r * 128 + k] : 0.f;
    }

    // ---- hid = x @ W1 + b1 ----
    {
        int j = tid;
        float acc[RPB];
        float bj = b1[j];
#pragma unroll
        for (int u = 0; u < RPB; u++) acc[u] = bj;
        for (int k0 = 0; k0 < 128; k0 += 32) {
            __syncthreads();
            for (int i = tid; i < 8192; i += 256)
                wt[i] = W1[(k0 + (i >> 8)) * 256 + (i & 255)];
            __syncthreads();
#pragma unroll 8
            for (int kk = 0; kk < 32; kk++) {
                float w = wt[kk * 256 + j];
#pragma unroll
                for (int u = 0; u < RPB; u++) acc[u] += sx[u * 128 + k0 + kk] * w;
            }
        }
#pragma unroll
        for (int u = 0; u < RPB; u++) shid[u * 256 + j] = acc[u];
    }
    __syncthreads();

    // ---- msg = x + hid @ W2 + b2 ----
    {
        int j = tid & 127, half = tid >> 7;
        float acc[RPB];
#pragma unroll
        for (int u = 0; u < RPB; u++) acc[u] = 0.f;
        for (int t = 0; t < 4; t++) {
            __syncthreads();
            for (int i = tid; i < 8192; i += 256) {
                int hh = i >> 12, loc = i & 4095, row = loc >> 7, col = loc & 127;
                wt[i] = W2[(hh * 128 + t * 32 + row) * 128 + col];
            }
            __syncthreads();
            const float* w = wt + half * 4096;
            int kbase = half * 128 + t * 32;
#pragma unroll 8
            for (int kk = 0; kk < 32; kk++) {
                float wv = w[kk * 128 + j];
#pragma unroll
                for (int u = 0; u < RPB; u++) acc[u] += shid[u * 256 + kbase + kk] * wv;
            }
        }
        __syncthreads();
        float* red = wt;
#pragma unroll
        for (int u = 0; u < RPB; u++) red[u * 256 + half * 128 + j] = acc[u];
        __syncthreads();
        if (half == 0) {
            float bj = b2[j];
#pragma unroll
            for (int u = 0; u < RPB; u++)
                smsg[u * 128 + j] = sx[u * 128 + j] + bj + red[u * 256 + j] + red[u * 256 + 128 + j];
        }
    }
    __syncthreads();

    // ---- P_side = msg @ Wr_side ----
    {
        int j = tid;
        for (int side = 0; side < 2; side++) {
            float acc[RPB];
#pragma unroll
            for (int u = 0; u < RPB; u++) acc[u] = 0.f;
            for (int k0 = 0; k0 < 128; k0 += 32) {
                __syncthreads();
                for (int i = tid; i < 8192; i += 256)
                    wt[i] = Wr[(side * 128 + k0 + (i >> 8)) * 256 + (i & 255)];
                __syncthreads();
#pragma unroll 8
                for (int kk = 0; kk < 32; kk++) {
                    float w = wt[kk * 256 + j];
#pragma unroll
                    for (int u = 0; u < RPB; u++) acc[u] += smsg[u * 128 + k0 + kk] * w;
                }
            }
            int c = (j >> 5) + side * 8, l = j & 31;
#pragma unroll
            for (int u = 0; u < RPB; u++) {
                int r = r0 + u;
                if (r < n_r) g_P[(c * n_r + r) * 32 + l] = acc[u];
            }
        }
    }
}

// ---------------- histogram ----------------
__global__ void k_hist(const int* __restrict__ h, const int* __restrict__ t, int E) {
    int e = blockIdx.x * blockDim.x + threadIdx.x;
    if (e < E) {
        atomicAdd(&g_cnt_h[h[e]], 1);
        atomicAdd(&g_cnt_t[t[e]], 1);
    }
}

// ---------------- scan over PADDED counts (pad to multiple of 4 edges) ----------------
__global__ void k_scan1(int n_e) {
    __shared__ int s[1024];
    int y = blockIdx.y;
    const int* cnt = y ? g_cnt_t : g_cnt_h;
    int* st = y ? g_starts_t : g_starts_h;
    int i = blockIdx.x * 1024 + threadIdx.x;
    int v = (i < n_e) ? ((cnt[i] + 3) & ~3) : 0;
    s[threadIdx.x] = v;
    __syncthreads();
    for (int o = 1; o < 1024; o <<= 1) {
        int tv = (threadIdx.x >= (unsigned)o) ? s[threadIdx.x - o] : 0;
        __syncthreads();
        s[threadIdx.x] += tv;
        __syncthreads();
    }
    if (i < n_e) st[i] = s[threadIdx.x];
    if (threadIdx.x == 1023) g_bsum[y][blockIdx.x] = s[1023];
}

__global__ void k_scan2(int nb) {
    if (threadIdx.x != 0) return;
    int y = blockIdx.x;
    int acc = 0;
    for (int b = 0; b < nb; b++) { int t = g_bsum[y][b]; g_bsum[y][b] = acc; acc += t; }
    g_bsum[y][nb] = acc;
}

__global__ void k_scan3(int n_e, int nb) {
    int y = blockIdx.y;
    const int* cnt = y ? g_cnt_t : g_cnt_h;
    int* st = y ? g_starts_t : g_starts_h;
    int* cur = y ? g_cur_t : g_cur_h;
    int i = blockIdx.x * 1024 + threadIdx.x;
    if (i < n_e) {
        int pc = (cnt[i] + 3) & ~3;
        int ex = st[i] - pc + g_bsum[y][blockIdx.x];
        st[i] = ex;
        cur[i] = ex;
    }
    if (i == 0) st[n_e] = g_bsum[y][nb];
}

// ---------------- place edges (off stored as BYTE offset r*128) ----------------
__global__ void k_place(const int* __restrict__ h, const int* __restrict__ t,
                        const int* __restrict__ rel, int E) {
    int e = blockIdx.x * blockDim.x + threadIdx.x;
    if (e >= E) return;
    int hn = h[e], tn = t[e], r = rel[e];
    float sr = g_sr[r];
    float lh = g_sh[hn] + sr; lh = (lh > 0.f) ? lh : 0.01f * lh;
    float lt = g_st[tn] + sr; lt = (lt > 0.f) ? lt : 0.01f * lt;
    float zh = __expf(lh), zt = __expf(lt);
    float ro = __int_as_float(r * 128);
    int ph = atomicAdd(&g_cur_h[hn], 1);
    g_pack_h[ph] = make_float2(zh, ro);
    int pt = atomicAdd(&g_cur_t[tn], 1);
    g_pack_t[pt] = make_float2(zt, ro);
}

// ---------------- per-node inverse denominators (batched loads, predicated adds) --------
__global__ void k_denom(int n_e) {
    int n = blockIdx.x * blockDim.x + threadIdx.x;
    if (n >= n_e) return;
    {
        int i = g_starts_h[n] >> 1, e4 = g_starts_h[n + 1] >> 1;
        const float4* p4 = (const float4*)g_pack_h;
        float S = 0.f;
        do {
            float4 b[4];
#pragma unroll
            for (int k = 0; k < 4; k++) b[k] = p4[i + k];
#pragma unroll
            for (int k = 0; k < 4; k++) if (i + k < e4) S += b[k].x + b[k].z;
            i += 4;
        } while (i < e4);
        g_inv_h[n] = 1.f / (S + 1e-16f);
    }
    {
        int i = g_starts_t[n] >> 1, e4 = g_starts_t[n + 1] >> 1;
        const float4* p4 = (const float4*)g_pack_t;
        float S = 0.f;
        do {
            float4 b[4];
#pragma unroll
            for (int k = 0; k < 4; k++) b[k] = p4[i + k];
#pragma unroll
            for (int k = 0; k < 4; k++) if (i + k < e4) S += b[k].x + b[k].z;
            i += 4;
        } while (i < e4);
        g_inv_t[n] = 1.f / (S + 1e-16f);
    }
}

// ---------------- main SpMM: full-node batch of 8 unpredicated LDG.128 (MLP=8),
// predicated FFMAs. Over-read is safe: pad slots are zero, foreign offs are valid smem.
__global__ __launch_bounds__(1024, 1) void k_main(const float* __restrict__ br,
                                                  float* __restrict__ out,
                                                  int n_e, int n_r) {
    extern __shared__ float sP[];  // n_r * 32 floats
    int pass = blockIdx.x;
    int nslices = gridDim.y;
    int ns_per = (n_e + nslices - 1) / nslices;
    int n0 = blockIdx.y * ns_per;
    int n1 = min(n0 + ns_per, n_e);
    int lane = threadIdx.x & 31;
    int warp = threadIdx.x >> 5;
    int nwarp = blockDim.x >> 5;
    float bv = br[pass * 32 + lane];
    const char* sPb = (const char*)(sP + lane);
    int chunk_words = n_r * 32;

    // ---- phase A: h side ----
    {
        const float4* s4 = (const float4*)(g_P + (size_t)pass * chunk_words);
        float4* d4 = (float4*)sP;
        for (int i = threadIdx.x; i < (chunk_words >> 2); i += blockDim.x) d4[i] = s4[i];
    }
    __syncthreads();
    {
        const float4* __restrict__ p4 = (const float4*)g_pack_h;
        int n = n0 + warp;
        if (n < n1) {
            int s0 = g_starts_h[n] >> 1;
            int s1 = g_starts_h[n + 1] >> 1;
            float inv = g_inv_h[n];
            while (true) {
                int nn = n + nwarp;
                int t0 = 0, t1 = 0; float tinv = 0.f;
                if (nn < n1) { t0 = g_starts_h[nn] >> 1; t1 = g_starts_h[nn + 1] >> 1; tinv = g_inv_h[nn]; }
                float acc = 0.f;
                int i = s0;
                do {
                    float4 b[8];
#pragma unroll
                    for (int k = 0; k < 8; k++) b[k] = p4[i + k];
#pragma unroll
                    for (int k = 0; k < 8; k++) {
                        if (i + k < s1) {
                            float v0 = *(const float*)(sPb + __float_as_int(b[k].y));
                            float v1 = *(const float*)(sPb + __float_as_int(b[k].w));
                            acc = fmaf(b[k].x, v0, acc);
                            acc = fmaf(b[k].z, v1, acc);
                        }
                    }
                    i += 8;
                } while (i < s1);
                out[(size_t)n * 256 + pass * 32 + lane] = bv + acc * inv;
                if (nn >= n1) break;
                n = nn; s0 = t0; s1 = t1; inv = tinv;
            }
        }
    }
    __syncthreads();

    // ---- phase B: t side (RMW) ----
    {
        const float4* s4 = (const float4*)(g_P + (size_t)(8 + pass) * chunk_words);
        float4* d4 = (float4*)sP;
        for (int i = threadIdx.x; i < (chunk_words >> 2); i += blockDim.x) d4[i] = s4[i];
    }
    __syncthreads();
    {
        const float4* __restrict__ p4 = (const float4*)g_pack_t;
        int n = n0 + warp;
        if (n < n1) {
            int s0 = g_starts_t[n] >> 1;
            int s1 = g_starts_t[n + 1] >> 1;
            float inv = g_inv_t[n];
            while (true) {
                int nn = n + nwarp;
                int t0 = 0, t1 = 0; float tinv = 0.f;
                if (nn < n1) { t0 = g_starts_t[nn] >> 1; t1 = g_starts_t[nn + 1] >> 1; tinv = g_inv_t[nn]; }
                float acc = 0.f;
                int i = s0;
                do {
                    float4 b[8];
#pragma unroll
                    for (int k = 0; k < 8; k++) b[k] = p4[i + k];
#pragma unroll
                    for (int k = 0; k < 8; k++) {
                        if (i + k < s1) {
                            float v0 = *(const float*)(sPb + __float_as_int(b[k].y));
                            float v1 = *(const float*)(sPb + __float_as_int(b[k].w));
                            acc = fmaf(b[k].x, v0, acc);
                            acc = fmaf(b[k].z, v1, acc);
                        }
                    }
                    i += 8;
                } while (i < s1);
                size_t o = (size_t)n * 256 + pass * 32 + lane;
                out[o] += acc * inv;
                if (nn >= n1) break;
                n = nn; s0 = t0; s1 = t1; inv = tinv;
            }
        }
    }
}

// ---------------- launch ----------------
extern "C" void kernel_launch(void* const* d_in, const int* in_sizes, int n_in,
                              void* d_out, int out_size) {
    const float* xe  = (const float*)d_in[0];
    const float* xr  = (const float*)d_in[1];
    const int*   ei  = (const int*)d_in[2];
    const int*   rel = (const int*)d_in[3];
    const float* wah = (const float*)d_in[5];
    const float* wat = (const float*)d_in[6];
    const float* war = (const float*)d_in[7];
    const float* W1  = (const float*)d_in[8];
    const float* b1  = (const float*)d_in[9];
    const float* W2  = (const float*)d_in[10];
    const float* b2  = (const float*)d_in[11];
    const float* Wr  = (const float*)d_in[12];
    const float* br  = (const float*)d_in[13];
    float* out = (float*)d_out;

    int n_e = in_sizes[0] / 128;
    int n_r = in_sizes[1] / 128;
    int E   = in_sizes[3];
    const int* h = ei;
    const int* t = ei + E;
    int nb = (n_e + 1023) / 1024;

    cudaFuncSetAttribute(k_main, cudaFuncAttributeMaxDynamicSharedMemorySize, 131072);

    k_zero<<<(n_e + 255) / 256, 256>>>(n_e);
    k_scores<<<((n_e + n_r) * 32 + 255) / 256, 256>>>((const float4*)xe, (const float4*)xr,
                                                      (const float4*)wah, (const float4*)wat,
                                                      (const float4*)war, n_e, n_r);
    k_rgemm<<<(n_r + RPB - 1) / RPB, 256>>>(xr, W1, b1, W2, b2, Wr, n_r);
    k_hist<<<(E + 255) / 256, 256>>>(h, t, E);
    k_scan1<<<dim3(nb, 2), 1024>>>(n_e);
    k_scan2<<<2, 32>>>(nb);
    k_scan3<<<dim3(nb, 2), 1024>>>(n_e, nb);
    k_place<<<(E + 255) / 256, 256>>>(h, t, rel, E);
    k_denom<<<(n_e + 127) / 128, 128>>>(n_e);

    dim3 g(8, 18);
    k_main<<<g, 1024, (size_t)n_r * 32 * sizeof(float)>>>(br, out, n_e, n_r);
}

// round 5
// speedup vs baseline: 1.6373x; 1.6373x over previous
#include <cuda_runtime.h>
#include <cuda_fp16.h>
#include <math.h>

#define MAX_NE 100000
#define MAX_NR 1000
#define MAX_E  1000000
#define PACK_CAP 1310784   // E + 3*N_E padding + over-read guard

// ---------------- scratch ----------------
__device__ float  g_sh[MAX_NE];
__device__ float  g_st[MAX_NE];
__device__ float  g_sr[MAX_NR];
// fp16 P tables: [side(2)][chunk(4)][rel][64 halves]; h side 0..3, t side 4..7
__device__ __half g_P16[8 * MAX_NR * 64];
__device__ int    g_cnt_h[MAX_NE];
__device__ int    g_cnt_t[MAX_NE];
__device__ int    g_starts_h[MAX_NE + 1];  // PADDED exclusive starts (multiples of 4 edges)
__device__ int    g_starts_t[MAX_NE + 1];
__device__ int    g_cur_h[MAX_NE];
__device__ int    g_cur_t[MAX_NE];
__device__ float  g_inv_h[MAX_NE];
__device__ float  g_inv_t[MAX_NE];
// pad slots are NEVER written: BSS-zero => {z=0, off=0}, mathematically inert.
__device__ float2 g_pack_h[PACK_CAP];
__device__ float2 g_pack_t[PACK_CAP];
__device__ int    g_bsum[2][160];

// ---------------- init ----------------
__global__ void k_zero(int n_e) {
    int i = blockIdx.x * blockDim.x + threadIdx.x;
    if (i < n_e) { g_cnt_h[i] = 0; g_cnt_t[i] = 0; }
}

// ---------------- fused attention scores (nodes then rels), warp per row ----------------
__global__ void k_scores(const float4* __restrict__ xe, const float4* __restrict__ xr,
                         const float4* __restrict__ wah4, const float4* __restrict__ wat4,
                         const float4* __restrict__ war4, int n_e, int n_r) {
    int gw = (blockIdx.x * blockDim.x + threadIdx.x) >> 5;
    int lane = threadIdx.x & 31;
    if (gw < n_e) {
        float4 v = xe[(size_t)gw * 32 + lane];
        float4 a = wah4[lane];
        float4 b = wat4[lane];
        float da = v.x * a.x + v.y * a.y + v.z * a.z + v.w * a.w;
        float db = v.x * b.x + v.y * b.y + v.z * b.z + v.w * b.w;
#pragma unroll
        for (int o = 16; o > 0; o >>= 1) {
            da += __shfl_xor_sync(0xffffffffu, da, o);
            db += __shfl_xor_sync(0xffffffffu, db, o);
        }
        if (lane == 0) { g_sh[gw] = da; g_st[gw] = db; }
    } else if (gw < n_e + n_r) {
        int r = gw - n_e;
        float4 v = xr[r * 32 + lane];
        float4 a = war4[lane];
        float d = v.x * a.x + v.y * a.y + v.z * a.z + v.w * a.w;
#pragma unroll
        for (int o = 16; o > 0; o >>= 1) d += __shfl_xor_sync(0xffffffffu, d, o);
        if (lane == 0) g_sr[r] = d;
    }
}

// ---------------- fused relation pipeline: x_r -> hid -> msg -> P (fp16) ----------------
#define RPB 8
__global__ __launch_bounds__(256) void k_rgemm(const float* __restrict__ xr,
                                               const float* __restrict__ W1, const float* __restrict__ b1,
                                               const float* __restrict__ W2, const float* __restrict__ b2,
                                               const float* __restrict__ Wr, int n_r) {
    __shared__ float sx[RPB * 128];
    __shared__ float shid[RPB * 256];
    __shared__ float smsg[RPB * 128];
    __shared__ float wt[32 * 256];
    int r0 = blockIdx.x * RPB;
    int tid = threadIdx.x;

    for (int i = tid; i < RPB * 128; i += 256) {
        int rr = i >> 7, k = i & 127, r = r0 + rr;
        sx[i] = (r < n_r) ? xr[r * 128 + k] : 0.f;
    }

    // ---- hid = x @ W1 + b1 ----
    {
        int j = tid;
        float acc[RPB];
        float bj = b1[j];
#pragma unroll
        for (int u = 0; u < RPB; u++) acc[u] = bj;
        for (int k0 = 0; k0 < 128; k0 += 32) {
            __syncthreads();
            for (int i = tid; i < 8192; i += 256)
                wt[i] = W1[(k0 + (i >> 8)) * 256 + (i & 255)];
            __syncthreads();
#pragma unroll 8
            for (int kk = 0; kk < 32; kk++) {
                float w = wt[kk * 256 + j];
#pragma unroll
                for (int u = 0; u < RPB; u++) acc[u] += sx[u * 128 + k0 + kk] * w;
            }
        }
#pragma unroll
        for (int u = 0; u < RPB; u++) shid[u * 256 + j] = acc[u];
    }
    __syncthreads();

    // ---- msg = x + hid @ W2 + b2 ----
    {
        int j = tid & 127, half = tid >> 7;
        float acc[RPB];
#pragma unroll
        for (int u = 0; u < RPB; u++) acc[u] = 0.f;
        for (int t = 0; t < 4; t++) {
            __syncthreads();
            for (int i = tid; i < 8192; i += 256) {
                int hh = i >> 12, loc = i & 4095, row = loc >> 7, col = loc & 127;
                wt[i] = W2[(hh * 128 + t * 32 + row) * 128 + col];
            }
            __syncthreads();
            const float* w = wt + half * 4096;
            int kbase = half * 128 + t * 32;
#pragma unroll 8
            for (int kk = 0; kk < 32; kk++) {
                float wv = w[kk * 128 + j];
#pragma unroll
                for (int u = 0; u < RPB; u++) acc[u] += shid[u * 256 + kbase + kk] * wv;
            }
        }
        __syncthreads();
        float* red = wt;
#pragma unroll
        for (int u = 0; u < RPB; u++) red[u * 256 + half * 128 + j] = acc[u];
        __syncthreads();
        if (half == 0) {
            float bj = b2[j];
#pragma unroll
            for (int u = 0; u < RPB; u++)
                smsg[u * 128 + j] = sx[u * 128 + j] + bj + red[u * 256 + j] + red[u * 256 + 128 + j];
        }
    }
    __syncthreads();

    // ---- P_side = msg @ Wr_side -> fp16 chunked [side*4 + (j>>6)][rel][j&63] ----
    {
        int j = tid;
        for (int side = 0; side < 2; side++) {
            float acc[RPB];
#pragma unroll
            for (int u = 0; u < RPB; u++) acc[u] = 0.f;
            for (int k0 = 0; k0 < 128; k0 += 32) {
                __syncthreads();
                for (int i = tid; i < 8192; i += 256)
                    wt[i] = Wr[(side * 128 + k0 + (i >> 8)) * 256 + (i & 255)];
                __syncthreads();
#pragma unroll 8
                for (int kk = 0; kk < 32; kk++) {
                    float w = wt[kk * 256 + j];
#pragma unroll
                    for (int u = 0; u < RPB; u++) acc[u] += smsg[u * 128 + k0 + kk] * w;
                }
            }
            int c = (j >> 6) + side * 4, l = j & 63;
#pragma unroll
            for (int u = 0; u < RPB; u++) {
                int r = r0 + u;
                if (r < n_r) g_P16[((size_t)c * n_r + r) * 64 + l] = __float2half_rn(acc[u]);
            }
        }
    }
}

// ---------------- histogram ----------------
__global__ void k_hist(const int* __restrict__ h, const int* __restrict__ t, int E) {
    int e = blockIdx.x * blockDim.x + threadIdx.x;
    if (e < E) {
        atomicAdd(&g_cnt_h[h[e]], 1);
        atomicAdd(&g_cnt_t[t[e]], 1);
    }
}

// ---------------- scan over PADDED counts (multiples of 4 edges) ----------------
__global__ void k_scan1(int n_e) {
    __shared__ int s[1024];
    int y = blockIdx.y;
    const int* cnt = y ? g_cnt_t : g_cnt_h;
    int* st = y ? g_starts_t : g_starts_h;
    int i = blockIdx.x * 1024 + threadIdx.x;
    int v = (i < n_e) ? ((cnt[i] + 3) & ~3) : 0;
    s[threadIdx.x] = v;
    __syncthreads();
    for (int o = 1; o < 1024; o <<= 1) {
        int tv = (threadIdx.x >= (unsigned)o) ? s[threadIdx.x - o] : 0;
        __syncthreads();
        s[threadIdx.x] += tv;
        __syncthreads();
    }
    if (i < n_e) st[i] = s[threadIdx.x];
    if (threadIdx.x == 1023) g_bsum[y][blockIdx.x] = s[1023];
}

__global__ void k_scan2(int nb) {
    if (threadIdx.x != 0) return;
    int y = blockIdx.x;
    int acc = 0;
    for (int b = 0; b < nb; b++) { int t = g_bsum[y][b]; g_bsum[y][b] = acc; acc += t; }
    g_bsum[y][nb] = acc;
}

__global__ void k_scan3(int n_e, int nb) {
    int y = blockIdx.y;
    const int* cnt = y ? g_cnt_t : g_cnt_h;
    int* st = y ? g_starts_t : g_starts_h;
    int* cur = y ? g_cur_t : g_cur_h;
    int i = blockIdx.x * 1024 + threadIdx.x;
    if (i < n_e) {
        int pc = (cnt[i] + 3) & ~3;
        int ex = st[i] - pc + g_bsum[y][blockIdx.x];
        st[i] = ex;
        cur[i] = ex;
    }
    if (i == 0) st[n_e] = g_bsum[y][nb];
}

// ---------------- place edges (off stored as BYTE offset r*128 in the fp16 table) -------
__global__ void k_place(const int* __restrict__ h, const int* __restrict__ t,
                        const int* __restrict__ rel, int E) {
    int e = blockIdx.x * blockDim.x + threadIdx.x;
    if (e >= E) return;
    int hn = h[e], tn = t[e], r = rel[e];
    float sr = g_sr[r];
    float lh = g_sh[hn] + sr; lh = (lh > 0.f) ? lh : 0.01f * lh;
    float lt = g_st[tn] + sr; lt = (lt > 0.f) ? lt : 0.01f * lt;
    float zh = __expf(lh), zt = __expf(lt);
    float ro = __int_as_float(r * 128);
    int ph = atomicAdd(&g_cur_h[hn], 1);
    g_pack_h[ph] = make_float2(zh, ro);
    int pt = atomicAdd(&g_cur_t[tn], 1);
    g_pack_t[pt] = make_float2(zt, ro);
}

// ---------------- per-node inverse denominators ----------------
__global__ void k_denom(int n_e) {
    int n = blockIdx.x * blockDim.x + threadIdx.x;
    if (n >= n_e) return;
    {
        int i = g_starts_h[n] >> 1, e4 = g_starts_h[n + 1] >> 1;
        const float4* p4 = (const float4*)g_pack_h;
        float S = 0.f;
        do {
            float4 b[4];
#pragma unroll
            for (int k = 0; k < 4; k++) b[k] = p4[i + k];
#pragma unroll
            for (int k = 0; k < 4; k++) if (i + k < e4) S += b[k].x + b[k].z;
            i += 4;
        } while (i < e4);
        g_inv_h[n] = 1.f / (S + 1e-16f);
    }
    {
        int i = g_starts_t[n] >> 1, e4 = g_starts_t[n + 1] >> 1;
        const float4* p4 = (const float4*)g_pack_t;
        float S = 0.f;
        do {
            float4 b[4];
#pragma unroll
            for (int k = 0; k < 4; k++) b[k] = p4[i + k];
#pragma unroll
            for (int k = 0; k < 4; k++) if (i + k < e4) S += b[k].x + b[k].z;
            i += 4;
        } while (i < e4);
        g_inv_t[n] = 1.f / (S + 1e-16f);
    }
}

// ---------------- main SpMM: 64 feats/pass (fp16 table), round-2 inner loop shape -------
// warp per node, lane covers 2 consecutive feats (fp16x2 LDS + cvt + 2 fp32 FFMA).
__global__ __launch_bounds__(1024, 1) void k_main(const float2* __restrict__ br2,
                                                  float2* __restrict__ out2,
                                                  int n_e, int n_r) {
    extern __shared__ __half sP[];  // n_r * 64 halves = 128000 B
    int pass = blockIdx.x;          // 0..3 feature chunk (64 feats)
    int nslices = gridDim.y;
    int ns_per = (n_e + nslices - 1) / nslices;
    int n0 = blockIdx.y * ns_per;
    int n1 = min(n0 + ns_per, n_e);
    int lane = threadIdx.x & 31;
    int warp = threadIdx.x >> 5;
    int nwarp = blockDim.x >> 5;
    float2 bv = br2[pass * 32 + lane];
    const char* sPb = (const char*)sP + lane * 4;  // this lane's fp16x2 column
    int chunk_halves = n_r * 64;

    // ---- phase A: h side ----
    {
        const uint4* s4 = (const uint4*)(g_P16 + (size_t)pass * chunk_halves);
        uint4* d4 = (uint4*)sP;
        for (int i = threadIdx.x; i < (chunk_halves >> 3); i += blockDim.x) d4[i] = s4[i];
    }
    __syncthreads();
    {
        const float2* __restrict__ pk = g_pack_h;
        int n = n0 + warp;
        if (n < n1) {
            int s0 = g_starts_h[n];
            int s1 = g_starts_h[n + 1];
            float inv = g_inv_h[n];
            while (true) {
                int nn = n + nwarp;
                int t0 = 0, t1 = 0; float tinv = 0.f;
                if (nn < n1) { t0 = g_starts_h[nn]; t1 = g_starts_h[nn + 1]; tinv = g_inv_h[nn]; }
                float ax = 0.f, ay = 0.f;
                for (int i = s0; i < s1; i += 8) {
#pragma unroll
                    for (int u = 0; u < 8; u++) {
                        int j = i + u;
                        float2 p = (j < s1) ? pk[j] : make_float2(0.f, 0.f);
                        __half2 hv = *(const __half2*)(sPb + __float_as_int(p.y));
                        float2 v = __half22float2(hv);
                        ax = fmaf(p.x, v.x, ax);
                        ay = fmaf(p.x, v.y, ay);
                    }
                }
                float2 o;
                o.x = bv.x + ax * inv;
                o.y = bv.y + ay * inv;
                out2[(size_t)n * 128 + pass * 32 + lane] = o;
                if (nn >= n1) break;
                n = nn; s0 = t0; s1 = t1; inv = tinv;
            }
        }
    }
    __syncthreads();

    // ---- phase B: t side (RMW) ----
    {
        const uint4* s4 = (const uint4*)(g_P16 + (size_t)(4 + pass) * chunk_halves);
        uint4* d4 = (uint4*)sP;
        for (int i = threadIdx.x; i < (chunk_halves >> 3); i += blockDim.x) d4[i] = s4[i];
    }
    __syncthreads();
    {
        const float2* __restrict__ pk = g_pack_t;
        int n = n0 + warp;
        if (n < n1) {
            int s0 = g_starts_t[n];
            int s1 = g_starts_t[n + 1];
            float inv = g_inv_t[n];
            while (true) {
                int nn = n + nwarp;
                int t0 = 0, t1 = 0; float tinv = 0.f;
                if (nn < n1) { t0 = g_starts_t[nn]; t1 = g_starts_t[nn + 1]; tinv = g_inv_t[nn]; }
                float ax = 0.f, ay = 0.f;
                for (int i = s0; i < s1; i += 8) {
#pragma unroll
                    for (int u = 0; u < 8; u++) {
                        int j = i + u;
                        float2 p = (j < s1) ? pk[j] : make_float2(0.f, 0.f);
                        __half2 hv = *(const __half2*)(sPb + __float_as_int(p.y));
                        float2 v = __half22float2(hv);
                        ax = fmaf(p.x, v.x, ax);
                        ay = fmaf(p.x, v.y, ay);
                    }
                }
                size_t oi = (size_t)n * 128 + pass * 32 + lane;
                float2 o = out2[oi];
                o.x += ax * inv;
                o.y += ay * inv;
                out2[oi] = o;
                if (nn >= n1) break;
                n = nn; s0 = t0; s1 = t1; inv = tinv;
            }
        }
    }
}

// ---------------- launch ----------------
extern "C" void kernel_launch(void* const* d_in, const int* in_sizes, int n_in,
                              void* d_out, int out_size) {
    const float* xe  = (const float*)d_in[0];
    const float* xr  = (const float*)d_in[1];
    const int*   ei  = (const int*)d_in[2];
    const int*   rel = (const int*)d_in[3];
    const float* wah = (const float*)d_in[5];
    const float* wat = (const float*)d_in[6];
    const float* war = (const float*)d_in[7];
    const float* W1  = (const float*)d_in[8];
    const float* b1  = (const float*)d_in[9];
    const float* W2  = (const float*)d_in[10];
    const float* b2  = (const float*)d_in[11];
    const float* Wr  = (const float*)d_in[12];
    const float* br  = (const float*)d_in[13];
    float* out = (float*)d_out;

    int n_e = in_sizes[0] / 128;
    int n_r = in_sizes[1] / 128;
    int E   = in_sizes[3];
    const int* h = ei;
    const int* t = ei + E;
    int nb = (n_e + 1023) / 1024;

    cudaFuncSetAttribute(k_main, cudaFuncAttributeMaxDynamicSharedMemorySize, 131072);

    k_zero<<<(n_e + 255) / 256, 256>>>(n_e);
    k_scores<<<((n_e + n_r) * 32 + 255) / 256, 256>>>((const float4*)xe, (const float4*)xr,
                                                      (const float4*)wah, (const float4*)wat,
                                                      (const float4*)war, n_e, n_r);
    k_rgemm<<<(n_r + RPB - 1) / RPB, 256>>>(xr, W1, b1, W2, b2, Wr, n_r);
    k_hist<<<(E + 255) / 256, 256>>>(h, t, E);
    k_scan1<<<dim3(nb, 2), 1024>>>(n_e);
    k_scan2<<<2, 32>>>(nb);
    k_scan3<<<dim3(nb, 2), 1024>>>(n_e, nb);
    k_place<<<(E + 255) / 256, 256>>>(h, t, rel, E);
    k_denom<<<(n_e + 127) / 128, 128>>>(n_e);

    dim3 g(4, 36);  // 144 blocks, 1/SM (128 KB smem)
    k_main<<<g, 1024, (size_t)n_r * 64 * sizeof(__half)>>>((const float2*)br, (float2*)out, n_e, n_r);
}